// round 5
// baseline (speedup 1.0000x reference)
#include <cuda_runtime.h>
#include <cuda_bf16.h>
#include <math.h>
#include <stdint.h>

#define B_ 2
#define S_ 2048
#define DM_ 2048
#define H_ 8
#define DH_ 128
#define INNER_ 1024
#define MROWS (B_*S_)   // 4096

// ---------------- scratch (device globals; no allocation allowed) ----------
__device__ float g_q[MROWS * INNER_];
__device__ float g_k[MROWS * INNER_];
__device__ float g_v[MROWS * INNER_];
__device__ float g_attn[MROWS * INNER_];
__device__ float g_beta[MROWS * H_];
__device__ float g_amean[H_];

// int8 quantized operands (+ per-row scales)
__device__ __align__(128) int8_t g_xq1[MROWS * DM_];
__device__ __align__(128) int8_t g_xq2[MROWS * DM_];
__device__ __align__(128) int8_t g_wq1[INNER_ * DM_];
__device__ __align__(128) int8_t g_wq2[INNER_ * DM_];
__device__ __align__(128) int8_t g_wk1[INNER_ * DM_];
__device__ __align__(128) int8_t g_wk2[INNER_ * DM_];
__device__ __align__(128) int8_t g_wv1[INNER_ * DM_];
__device__ __align__(128) int8_t g_wv2[INNER_ * DM_];
__device__ __align__(128) int8_t g_wo1[DM_ * INNER_];
__device__ __align__(128) int8_t g_wo2[DM_ * INNER_];
__device__ __align__(128) int8_t g_aq1[MROWS * INNER_];
__device__ __align__(128) int8_t g_aq2[MROWS * INNER_];
__device__ float g_sx[MROWS];
__device__ float g_swq[INNER_];
__device__ float g_swk[INNER_];
__device__ float g_swv[INNER_];
__device__ float g_swo[DM_];
__device__ float g_sat[MROWS];

__device__ __forceinline__ float sigmoidf_(float x) {
    return 1.0f / (1.0f + expf(-x));
}

// ======================= PTX helpers ==============================
__device__ __forceinline__ uint32_t smem_u32(const void* p) {
    uint32_t a;
    asm("{ .reg .u64 t; cvta.to.shared.u64 t, %1; cvt.u32.u64 %0, t; }"
        : "=r"(a) : "l"(p));
    return a;
}

#define CP_ASYNC16(dst, src) \
    asm volatile("cp.async.cg.shared.global [%0], [%1], 16;" :: "r"(dst), "l"(src) : "memory")
#define CP_COMMIT() asm volatile("cp.async.commit_group;" ::: "memory")
#define CP_WAIT(n)  asm volatile("cp.async.wait_group %0;" :: "n"(n) : "memory")

__device__ __forceinline__ void ldsm_x4(uint32_t& r0, uint32_t& r1, uint32_t& r2, uint32_t& r3,
                                        uint32_t addr) {
    asm volatile("ldmatrix.sync.aligned.m8n8.x4.shared.b16 {%0,%1,%2,%3}, [%4];"
        : "=r"(r0), "=r"(r1), "=r"(r2), "=r"(r3) : "r"(addr));
}

__device__ __forceinline__ void imma16832(int* c, const uint32_t* a, uint32_t b0, uint32_t b1) {
    asm volatile(
        "mma.sync.aligned.m16n8k32.row.col.s32.s8.s8.s32 "
        "{%0,%1,%2,%3}, {%4,%5,%6,%7}, {%8,%9}, {%0,%1,%2,%3};"
        : "+r"(c[0]), "+r"(c[1]), "+r"(c[2]), "+r"(c[3])
        : "r"(a[0]), "r"(a[1]), "r"(a[2]), "r"(a[3]), "r"(b0), "r"(b1));
}

// ======================= fp32 -> dual int8 quantization =====================
// a = s*(A1 + A2/256), s = rowmax/127.  One block per row.
__global__ __launch_bounds__(256) void quant_kernel(const float* __restrict__ src,
                                                    int K4,
                                                    int8_t* __restrict__ q1,
                                                    int8_t* __restrict__ q2,
                                                    float* __restrict__ scale) {
    __shared__ float4 xs[512];
    __shared__ float red[8];
    int row = blockIdx.x;
    int tid = threadIdx.x;
    const float4* s = (const float4*)(src + (size_t)row * K4 * 4);
    float am = 0.f;
    for (int i = tid; i < K4; i += 256) {
        float4 v = s[i];
        xs[i] = v;
        am = fmaxf(am, fmaxf(fmaxf(fabsf(v.x), fabsf(v.y)), fmaxf(fabsf(v.z), fabsf(v.w))));
    }
    #pragma unroll
    for (int o = 16; o; o >>= 1) am = fmaxf(am, __shfl_xor_sync(0xffffffffu, am, o));
    if ((tid & 31) == 0) red[tid >> 5] = am;
    __syncthreads();
    float amax = fmaxf(fmaxf(fmaxf(red[0], red[1]), fmaxf(red[2], red[3])),
                       fmaxf(fmaxf(red[4], red[5]), fmaxf(red[6], red[7])));
    float inv = amax > 0.f ? 127.f / amax : 0.f;
    char4* p1 = (char4*)(q1 + (size_t)row * K4 * 4);
    char4* p2 = (char4*)(q2 + (size_t)row * K4 * 4);
    for (int i = tid; i < K4; i += 256) {
        float4 v = xs[i];
        float qa[4] = {v.x * inv, v.y * inv, v.z * inv, v.w * inv};
        char c1[4], c2[4];
        #pragma unroll
        for (int j = 0; j < 4; j++) {
            float h = rintf(qa[j]);
            float l = rintf((qa[j] - h) * 256.f);
            l = fminf(fmaxf(l, -127.f), 127.f);
            c1[j] = (char)(int)h;
            c2[j] = (char)(int)l;
        }
        p1[i] = make_char4(c1[0], c1[1], c1[2], c1[3]);
        p2[i] = make_char4(c2[0], c2[1], c2[2], c2[3]);
    }
    if (tid == 0) scale[row] = amax * (1.f / 127.f);
}

// ======================= IMMA dual-int8 GEMM ================================
// C[M,N](fp32) = sA_m*sB_n*(A1B1 + (A1B2 + A2B1)/256), dropping A2B2/256^2.
// 128x64 CTA tile, k-chunk 128 bytes, 2-stage cp.async, 8 warps @ 64x16.
#define A_TILE 16384u                  // 128 rows x 128B
#define B_TILE 8192u                   // 64 rows x 128B
#define STG2 (2u*A_TILE + 2u*B_TILE)   // 48KB
#define GEMM_SMEM (2u * STG2)          // 96KB

__global__ __launch_bounds__(256, 2) void imma_gemm(
    const int8_t* __restrict__ A1, const int8_t* __restrict__ A2,
    const float* __restrict__ sA,
    const int8_t* __restrict__ B01, const int8_t* __restrict__ B02, const float* __restrict__ sB0,
    const int8_t* __restrict__ B11, const int8_t* __restrict__ B12, const float* __restrict__ sB1,
    const int8_t* __restrict__ B21, const int8_t* __restrict__ B22, const float* __restrict__ sB2,
    float* __restrict__ C0, float* __restrict__ C1, float* __restrict__ C2,
    int K, int ldc) {
    extern __shared__ char smem[];
    uint32_t sm = smem_u32(smem);
    int tid = threadIdx.x;
    int lane = tid & 31;
    int wid = tid >> 5;
    int wm = wid & 1;          // 2 M-blocks of 64
    int wn = wid >> 1;         // 4 N-blocks of 16
    int m0 = blockIdx.y * 128;
    int n0 = blockIdx.x * 64;

    const int8_t *Bq1, *Bq2;
    const float* sB;
    float* C;
    if (blockIdx.z == 0)      { Bq1 = B01; Bq2 = B02; sB = sB0; C = C0; }
    else if (blockIdx.z == 1) { Bq1 = B11; Bq2 = B12; sB = sB1; C = C1; }
    else                      { Bq1 = B21; Bq2 = B22; sB = sB2; C = C2; }

    int kiters = K >> 7;

    int accP[4][2][4], accM[4][2][4];
    #pragma unroll
    for (int i = 0; i < 4; i++)
        #pragma unroll
        for (int g = 0; g < 2; g++)
            #pragma unroll
            for (int t = 0; t < 4; t++) { accP[i][g][t] = 0; accM[i][g][t] = 0; }

    int lc = tid & 7;          // 16B chunk within 128B row
    int lr = tid >> 3;         // 0..31

    #define ISSUE_STAGE(ip, buf) do {                                          \
        int _k0 = (ip) << 7;                                                   \
        const int8_t* _a1 = A1 + (size_t)(m0 + lr) * K + _k0 + lc * 16;        \
        const int8_t* _a2 = A2 + (size_t)(m0 + lr) * K + _k0 + lc * 16;        \
        const int8_t* _b1 = Bq1 + (size_t)(n0 + lr) * K + _k0 + lc * 16;       \
        const int8_t* _b2 = Bq2 + (size_t)(n0 + lr) * K + _k0 + lc * 16;       \
        uint32_t _sb = sm + (buf) * STG2;                                      \
        _Pragma("unroll")                                                      \
        for (int _i = 0; _i < 4; _i++) {                                       \
            int _row = lr + 32 * _i;                                           \
            uint32_t _sw = ((uint32_t)_row << 7) + (((uint32_t)(lc ^ (_row & 7))) << 4); \
            size_t _go = (size_t)(32 * _i) * K;                                \
            CP_ASYNC16(_sb + _sw,            _a1 + _go);                       \
            CP_ASYNC16(_sb + A_TILE + _sw,   _a2 + _go);                       \
        }                                                                      \
        _Pragma("unroll")                                                      \
        for (int _i = 0; _i < 2; _i++) {                                       \
            int _row = lr + 32 * _i;                                           \
            uint32_t _sw = ((uint32_t)_row << 7) + (((uint32_t)(lc ^ (_row & 7))) << 4); \
            size_t _go = (size_t)(32 * _i) * K;                                \
            CP_ASYNC16(_sb + 2*A_TILE + _sw,          _b1 + _go);              \
            CP_ASYNC16(_sb + 2*A_TILE + B_TILE + _sw, _b2 + _go);              \
        }                                                                      \
    } while (0)

    ISSUE_STAGE(0, 0); CP_COMMIT();

    for (int it = 0; it < kiters; ++it) {
        if (it + 1 < kiters) {
            ISSUE_STAGE(it + 1, (it + 1) & 1);
            CP_COMMIT();
            CP_WAIT(1);
        } else {
            CP_WAIT(0);
        }
        __syncthreads();

        uint32_t sa1 = sm + (it & 1) * STG2;
        uint32_t sa2 = sa1 + A_TILE;
        uint32_t sb1 = sa1 + 2 * A_TILE;
        uint32_t sb2 = sb1 + B_TILE;

        #pragma unroll
        for (int ks = 0; ks < 4; ++ks) {
            int ch = ks * 2 + (lane >> 4);
            int rowB = wn * 16 + (lane & 7) + ((lane >> 3) & 1) * 8;
            uint32_t offB = ((uint32_t)rowB << 7) + (((uint32_t)(ch ^ (rowB & 7))) << 4);
            uint32_t p0, p1, p2, p3, q0, q1, q2, q3;
            ldsm_x4(p0, p1, p2, p3, sb1 + offB);
            ldsm_x4(q0, q1, q2, q3, sb2 + offB);
            #pragma unroll
            for (int mt = 0; mt < 4; ++mt) {
                int rowA = wm * 64 + mt * 16 + (lane & 7) + ((lane >> 3) & 1) * 8;
                uint32_t offA = ((uint32_t)rowA << 7) + (((uint32_t)(ch ^ (rowA & 7))) << 4);
                uint32_t a1f[4], a2f[4];
                ldsm_x4(a1f[0], a1f[1], a1f[2], a1f[3], sa1 + offA);
                ldsm_x4(a2f[0], a2f[1], a2f[2], a2f[3], sa2 + offA);
                imma16832(accP[mt][0], a1f, p0, p2);
                imma16832(accP[mt][1], a1f, p1, p3);
                imma16832(accM[mt][0], a1f, q0, q2);
                imma16832(accM[mt][1], a1f, q1, q3);
                imma16832(accM[mt][0], a2f, p0, p2);
                imma16832(accM[mt][1], a2f, p1, p3);
            }
        }
        __syncthreads();
    }

    // -------- epilogue: dequantize + store --------
    const float inv256 = 1.f / 256.f;
    #pragma unroll
    for (int mt = 0; mt < 4; ++mt) {
        int m = m0 + wm * 64 + mt * 16 + (lane >> 2);
        float salo = sA[m];
        float sahi = sA[m + 8];
        #pragma unroll
        for (int g = 0; g < 2; ++g) {
            int n = n0 + wn * 16 + g * 8 + (lane & 3) * 2;
            float sb0v = sB[n], sb1v = sB[n + 1];
            float* p = C + (size_t)m * ldc + n;
            float v0 = salo * sb0v * ((float)accP[mt][g][0] + (float)accM[mt][g][0] * inv256);
            float v1 = salo * sb1v * ((float)accP[mt][g][1] + (float)accM[mt][g][1] * inv256);
            float v2 = sahi * sb0v * ((float)accP[mt][g][2] + (float)accM[mt][g][2] * inv256);
            float v3 = sahi * sb1v * ((float)accP[mt][g][3] + (float)accM[mt][g][3] * inv256);
            *(float2*)p = make_float2(v0, v1);
            *(float2*)(p + 8 * (size_t)ldc) = make_float2(v2, v3);
        }
    }
    #undef ISSUE_STAGE
}

// ---------------- alpha_mean per head ----------------
__global__ void amean_kernel(const float* __restrict__ alpha_log) {
    int w = threadIdx.x >> 5;
    int lane = threadIdx.x & 31;
    float s = 0.f;
    for (int d = lane; d < DH_; d += 32)
        s += sigmoidf_(alpha_log[w * DH_ + d]);
    #pragma unroll
    for (int o = 16; o; o >>= 1) s += __shfl_xor_sync(0xffffffffu, s, o);
    if (lane == 0) g_amean[w] = s / (float)DH_;
}

// ---------------- beta = sigmoid(x @ Wb^T + bb) ----------------
__global__ __launch_bounds__(256) void beta_kernel(const float* __restrict__ x,
                                                   const float* __restrict__ Wb,
                                                   const float* __restrict__ bb,
                                                   float* __restrict__ beta) {
    __shared__ float xs[DM_];
    int row = blockIdx.x;
    for (int i = threadIdx.x; i < DM_; i += 256)
        xs[i] = x[row * DM_ + i];
    __syncthreads();
    int w = threadIdx.x >> 5;
    int lane = threadIdx.x & 31;
    const float* wr = Wb + w * DM_;
    float sum = 0.f;
    for (int i = lane; i < DM_; i += 32)
        sum += xs[i] * wr[i];
    #pragma unroll
    for (int o = 16; o; o >>= 1) sum += __shfl_xor_sync(0xffffffffu, sum, o);
    if (lane == 0) beta[row * H_ + w] = sigmoidf_(sum + bb[w]);
}

// ---------------- RoPE in-place on q and k ----------------
__global__ void rope_kernel(float* __restrict__ q, float* __restrict__ k) {
    int idx = blockIdx.x * blockDim.x + threadIdx.x;
    int j = idx & 63;
    int h = (idx >> 6) & (H_ - 1);
    int row = idx >> 9;
    int s = row & (S_ - 1);
    float ex = (float)(2 * j) * (1.0f / (float)DH_);
    float inv = powf(10000.0f, -ex);
    float ang = (float)s * inv;
    float sn, c;
    sincosf(ang, &sn, &c);
    int base = row * INNER_ + h * DH_ + j;
    float x1 = q[base], x2 = q[base + 64];
    q[base]      = x1 * c - x2 * sn;
    q[base + 64] = x2 * c + x1 * sn;
    x1 = k[base]; x2 = k[base + 64];
    k[base]      = x1 * c - x2 * sn;
    k[base + 64] = x2 * c + x1 * sn;
}

// ---------------- windowed decay attention ----------------
#define WIN_ 32
__global__ __launch_bounds__(256) void attn_kernel(const float* __restrict__ q,
                                                   const float* __restrict__ k,
                                                   const float* __restrict__ v,
                                                   const float* __restrict__ beta,
                                                   float* __restrict__ attn) {
    int gw = (blockIdx.x * 256 + threadIdx.x) >> 5;
    int lane = threadIdx.x & 31;
    int s = gw & (S_ - 1);
    int h = (gw >> 11) & (H_ - 1);
    int b = gw >> 14;
    float am = g_amean[h];
    size_t colbase = (size_t)b * S_ * INNER_ + h * DH_ + lane * 4;
    float4 qv = *(const float4*)(q + colbase + (size_t)s * INNER_);
    float4 acc = make_float4(0.f, 0.f, 0.f, 0.f);
    float decay = 1.f;
    int t_lo = s - (WIN_ - 1); if (t_lo < 0) t_lo = 0;
    for (int t = s; t >= t_lo; t--) {
        float4 kv = *(const float4*)(k + colbase + (size_t)t * INNER_);
        float d = qv.x * kv.x + qv.y * kv.y + qv.z * kv.z + qv.w * kv.w;
        #pragma unroll
        for (int o = 16; o; o >>= 1) d += __shfl_xor_sync(0xffffffffu, d, o);
        float w = d * decay * beta[(b * S_ + t) * H_ + h];
        float4 vv = *(const float4*)(v + colbase + (size_t)t * INNER_);
        acc.x = fmaf(w, vv.x, acc.x);
        acc.y = fmaf(w, vv.y, acc.y);
        acc.z = fmaf(w, vv.z, acc.z);
        acc.w = fmaf(w, vv.w, acc.w);
        decay *= am;
    }
    *(float4*)(attn + colbase + (size_t)s * INNER_) = acc;
}

// ---------------- final recurrent state (windowed scan) ----------------
#define STWIN_ 128
__global__ __launch_bounds__(256) void state_kernel(const float* __restrict__ k,
                                                    const float* __restrict__ v,
                                                    const float* __restrict__ beta,
                                                    const float* __restrict__ alpha_log,
                                                    float* __restrict__ stout) {
    int b = blockIdx.x >> 3;
    int h = blockIdx.x & 7;
    int tid = threadIdx.x;
    int d = tid >> 1;
    int e0 = (tid & 1) * 64;
    __shared__ float ks[DH_], vs[DH_];
    float st[64];
    #pragma unroll
    for (int e = 0; e < 64; e++) st[e] = 0.f;
    float ad = sigmoidf_(alpha_log[h * DH_ + d]);
    for (int t = S_ - STWIN_; t < S_; t++) {
        __syncthreads();
        size_t base = (size_t)(b * S_ + t) * INNER_ + h * DH_;
        if (tid < 128) ks[tid] = k[base + tid];
        else           vs[tid - 128] = v[base + tid - 128];
        __syncthreads();
        float kb = ks[d] * beta[(b * S_ + t) * H_ + h];
        #pragma unroll
        for (int e = 0; e < 64; e++)
            st[e] = fmaf(ad, st[e], kb * vs[e0 + e]);
    }
    float* op = stout + ((size_t)(b * H_ + h) * DH_ + d) * DH_ + e0;
    #pragma unroll
    for (int e = 0; e < 64; e++) op[e] = st[e];
}

// ---------------- launch ----------------
extern "C" void kernel_launch(void* const* d_in, const int* in_sizes, int n_in,
                              void* d_out, int out_size) {
    const float* x         = (const float*)d_in[0];
    const float* Wq        = (const float*)d_in[1];
    const float* Wk        = (const float*)d_in[2];
    const float* Wv        = (const float*)d_in[3];
    const float* Wo        = (const float*)d_in[4];
    const float* Wb        = (const float*)d_in[5];
    const float* bb        = (const float*)d_in[6];
    const float* alpha_log = (const float*)d_in[7];
    float* out = (float*)d_out;

    float *q, *k, *v, *attn, *beta;
    cudaGetSymbolAddress((void**)&q,    g_q);
    cudaGetSymbolAddress((void**)&k,    g_k);
    cudaGetSymbolAddress((void**)&v,    g_v);
    cudaGetSymbolAddress((void**)&attn, g_attn);
    cudaGetSymbolAddress((void**)&beta, g_beta);
    int8_t *xq1, *xq2, *wq1, *wq2, *wk1, *wk2, *wv1, *wv2, *wo1, *wo2, *aq1, *aq2;
    float *sx, *swq, *swk, *swv, *swo, *sat;
    cudaGetSymbolAddress((void**)&xq1, g_xq1);
    cudaGetSymbolAddress((void**)&xq2, g_xq2);
    cudaGetSymbolAddress((void**)&wq1, g_wq1);
    cudaGetSymbolAddress((void**)&wq2, g_wq2);
    cudaGetSymbolAddress((void**)&wk1, g_wk1);
    cudaGetSymbolAddress((void**)&wk2, g_wk2);
    cudaGetSymbolAddress((void**)&wv1, g_wv1);
    cudaGetSymbolAddress((void**)&wv2, g_wv2);
    cudaGetSymbolAddress((void**)&wo1, g_wo1);
    cudaGetSymbolAddress((void**)&wo2, g_wo2);
    cudaGetSymbolAddress((void**)&aq1, g_aq1);
    cudaGetSymbolAddress((void**)&aq2, g_aq2);
    cudaGetSymbolAddress((void**)&sx,  g_sx);
    cudaGetSymbolAddress((void**)&swq, g_swq);
    cudaGetSymbolAddress((void**)&swk, g_swk);
    cudaGetSymbolAddress((void**)&swv, g_swv);
    cudaGetSymbolAddress((void**)&swo, g_swo);
    cudaGetSymbolAddress((void**)&sat, g_sat);

    cudaFuncSetAttribute(imma_gemm, cudaFuncAttributeMaxDynamicSharedMemorySize, GEMM_SMEM);

    amean_kernel<<<1, 256>>>(alpha_log);
    beta_kernel<<<MROWS, 256>>>(x, Wb, bb, beta);

    // fp32 -> dual int8 quantization (per-row scales)
    quant_kernel<<<MROWS, 256>>>(x,  DM_/4,   xq1, xq2, sx);
    quant_kernel<<<INNER_, 256>>>(Wq, DM_/4,  wq1, wq2, swq);
    quant_kernel<<<INNER_, 256>>>(Wk, DM_/4,  wk1, wk2, swk);
    quant_kernel<<<INNER_, 256>>>(Wv, DM_/4,  wv1, wv2, swv);
    quant_kernel<<<DM_, 256>>>(Wo, INNER_/4,  wo1, wo2, swo);

    // QKV: fused 3-way GEMM, M=4096, N=1024, K=2048
    dim3 gqkv(INNER_/64, MROWS/128, 3);
    imma_gemm<<<gqkv, 256, GEMM_SMEM>>>(xq1, xq2, sx,
                                        wq1, wq2, swq, wk1, wk2, swk, wv1, wv2, swv,
                                        q, k, v, DM_, INNER_);

    rope_kernel<<<(B_ * S_ * H_ * 64) / 256, 256>>>(q, k);
    attn_kernel<<<(B_ * H_ * S_) / 8, 256>>>(q, k, v, beta, attn);

    quant_kernel<<<MROWS, 256>>>(attn, INNER_/4, aq1, aq2, sat);

    // O-proj: M=4096, N=2048, K=1024
    dim3 gout(DM_/64, MROWS/128, 1);
    imma_gemm<<<gout, 256, GEMM_SMEM>>>(aq1, aq2, sat,
                                        wo1, wo2, swo, wo1, wo2, swo, wo1, wo2, swo,
                                        out, out, out, INNER_, DM_);

    state_kernel<<<B_ * H_, 256>>>(k, v, beta, alpha_log, out + (size_t)MROWS * DM_);
}

// round 6
// speedup vs baseline: 2.4196x; 2.4196x over previous
#include <cuda_runtime.h>
#include <cuda_fp16.h>
#include <math.h>
#include <stdint.h>

#define B_ 2
#define S_ 2048
#define DM_ 2048
#define H_ 8
#define DH_ 128
#define INNER_ 1024
#define MROWS (B_*S_)   // 4096

// ---------------- scratch (device globals; no allocation allowed) ----------
__device__ float g_q[MROWS * INNER_];
__device__ float g_k[MROWS * INNER_];
__device__ float g_v[MROWS * INNER_];
__device__ float g_beta[MROWS * H_];
__device__ float g_amean[H_];

__device__ __align__(128) __half g_xhi[MROWS * DM_];
__device__ __align__(128) __half g_xlo[MROWS * DM_];
__device__ __align__(128) __half g_wqh[INNER_ * DM_];
__device__ __align__(128) __half g_wkh[INNER_ * DM_];
__device__ __align__(128) __half g_wvh[INNER_ * DM_];
__device__ __align__(128) __half g_woh[DM_ * INNER_];
__device__ __align__(128) __half g_ahi[MROWS * INNER_];
__device__ __align__(128) __half g_alo[MROWS * INNER_];

__device__ __forceinline__ float sigmoidf_(float x) {
    return 1.0f / (1.0f + expf(-x));
}

// ======================= PTX helpers ==============================
__device__ __forceinline__ uint32_t smem_u32(const void* p) {
    uint32_t a;
    asm("{ .reg .u64 t; cvta.to.shared.u64 t, %1; cvt.u32.u64 %0, t; }"
        : "=r"(a) : "l"(p));
    return a;
}

#define CP_ASYNC16(dst, src) \
    asm volatile("cp.async.cg.shared.global [%0], [%1], 16;" :: "r"(dst), "l"(src) : "memory")
#define CP_COMMIT() asm volatile("cp.async.commit_group;" ::: "memory")
#define CP_WAIT(n)  asm volatile("cp.async.wait_group %0;" :: "n"(n) : "memory")

__device__ __forceinline__ void ldsm_x4(uint32_t& r0, uint32_t& r1, uint32_t& r2, uint32_t& r3,
                                        uint32_t addr) {
    asm volatile("ldmatrix.sync.aligned.m8n8.x4.shared.b16 {%0,%1,%2,%3}, [%4];"
        : "=r"(r0), "=r"(r1), "=r"(r2), "=r"(r3) : "r"(addr));
}

__device__ __forceinline__ void mma16816(float* c, const uint32_t* a, uint32_t b0, uint32_t b1) {
    asm volatile(
        "mma.sync.aligned.m16n8k16.row.col.f32.f16.f16.f32 "
        "{%0,%1,%2,%3}, {%4,%5,%6,%7}, {%8,%9}, {%0,%1,%2,%3};"
        : "+f"(c[0]), "+f"(c[1]), "+f"(c[2]), "+f"(c[3])
        : "r"(a[0]), "r"(a[1]), "r"(a[2]), "r"(a[3]), "r"(b0), "r"(b1));
}

// ======================= conversions ==========================
// fp32 -> fp16 hi/lo split (A operand: 22-bit exact)
__global__ void splitA_kernel(const float* __restrict__ src,
                              __half* __restrict__ hi,
                              __half* __restrict__ lo, int n4) {
    int i = blockIdx.x * blockDim.x + threadIdx.x;
    if (i >= n4) return;
    float4 v = ((const float4*)src)[i];
    __half h0 = __float2half(v.x);
    __half h1 = __float2half(v.y);
    __half h2 = __float2half(v.z);
    __half h3 = __float2half(v.w);
    __half l0 = __float2half(v.x - __half2float(h0));
    __half l1 = __float2half(v.y - __half2float(h1));
    __half l2 = __float2half(v.z - __half2float(h2));
    __half l3 = __float2half(v.w - __half2float(h3));
    __half2* hp = (__half2*)hi;
    __half2* lp = (__half2*)lo;
    hp[2*i]   = __half2(h0, h1);
    hp[2*i+1] = __half2(h2, h3);
    lp[2*i]   = __half2(l0, l1);
    lp[2*i+1] = __half2(l2, l3);
}

// fp32 -> fp16 (B operand: single rounding)
__global__ void cvt_kernel(const float* __restrict__ src,
                           __half* __restrict__ dst, int n4) {
    int i = blockIdx.x * blockDim.x + threadIdx.x;
    if (i >= n4) return;
    float4 v = ((const float4*)src)[i];
    __half2* p = (__half2*)dst;
    p[2*i]   = __half2(__float2half(v.x), __float2half(v.y));
    p[2*i+1] = __half2(__float2half(v.z), __float2half(v.w));
}

// ======================= fp16 2-pass HMMA GEMM ==============================
// C[M,N](fp32) = (Ah+Al)[M,K] @ Bh[N,K]^T  (Ah/Al fp16 split-2, Bh fp16)
// 128x128 CTA tile, k-chunk 64 halves (128B), 3-stage cp.async, 8 warps @ 64x32.
#define NSTG 3
#define TILE_B 16384u                 // one operand tile: 128 rows x 128B
#define STG_BYTES (3u * TILE_B)       // Ah | Al | Bh = 48KB
#define GEMM_SMEM (NSTG * STG_BYTES)  // 144KB

__global__ __launch_bounds__(256, 1) void hmma_gemm(
    const __half* __restrict__ Ah, const __half* __restrict__ Al,
    const __half* __restrict__ B0, const __half* __restrict__ B1,
    const __half* __restrict__ B2,
    float* __restrict__ C0, float* __restrict__ C1, float* __restrict__ C2,
    int K, int ldc) {
    extern __shared__ char smem[];
    uint32_t sm = smem_u32(smem);
    int tid = threadIdx.x;
    int lane = tid & 31;
    int wid = tid >> 5;
    int wm = wid & 1;          // 2 M-blocks of 64
    int wn = wid >> 1;         // 4 N-blocks of 32
    int m0 = blockIdx.y * 128;
    int n0 = blockIdx.x * 128;

    const __half* Bh;
    float* C;
    if (blockIdx.z == 0)      { Bh = B0; C = C0; }
    else if (blockIdx.z == 1) { Bh = B1; C = C1; }
    else                      { Bh = B2; C = C2; }

    int kiters = K >> 6;

    float acc[4][4][4];
    #pragma unroll
    for (int i = 0; i < 4; i++)
        #pragma unroll
        for (int j = 0; j < 4; j++)
            #pragma unroll
            for (int t = 0; t < 4; t++) acc[i][j][t] = 0.f;

    int lc = tid & 7;          // 16B chunk col within 128B row
    int lr = tid >> 3;         // 0..31

    #define ISSUE_STAGE(ip, buf) do {                                          \
        int _k0 = (ip) << 6;                                                   \
        const __half* _ah = Ah + (size_t)(m0 + lr) * K + _k0 + lc * 8;         \
        const __half* _al = Al + (size_t)(m0 + lr) * K + _k0 + lc * 8;         \
        const __half* _bh = Bh + (size_t)(n0 + lr) * K + _k0 + lc * 8;         \
        uint32_t _sb = sm + (buf) * STG_BYTES;                                 \
        _Pragma("unroll")                                                      \
        for (int _i = 0; _i < 4; _i++) {                                       \
            int _row = lr + 32 * _i;                                           \
            uint32_t _sw = ((uint32_t)_row << 7) + (((uint32_t)(lc ^ (_row & 7))) << 4); \
            size_t _go = (size_t)(32 * _i) * K;                                \
            CP_ASYNC16(_sb + _sw,              _ah + _go);                     \
            CP_ASYNC16(_sb + TILE_B + _sw,     _al + _go);                     \
            CP_ASYNC16(_sb + 2*TILE_B + _sw,   _bh + _go);                     \
        }                                                                      \
    } while (0)

    ISSUE_STAGE(0, 0); CP_COMMIT();
    if (kiters > 1) ISSUE_STAGE(1, 1);
    CP_COMMIT();

    int buf = 0;
    int ibuf = 2;
    for (int it = 0; it < kiters; ++it) {
        if (it + 2 < kiters) ISSUE_STAGE(it + 2, ibuf);
        CP_COMMIT();
        CP_WAIT(2);
        __syncthreads();

        uint32_t sah = sm + buf * STG_BYTES;
        uint32_t sal = sah + TILE_B;
        uint32_t sbh = sah + 2 * TILE_B;
        #pragma unroll
        for (int ks = 0; ks < 4; ++ks) {
            int ch = ks * 2 + (lane >> 4);
            uint32_t ah[4][4], al[4][4];
            #pragma unroll
            for (int mt = 0; mt < 4; ++mt) {
                int rowA = wm * 64 + mt * 16 + (lane & 7) + ((lane >> 3) & 1) * 8;
                uint32_t off = ((uint32_t)rowA << 7) + (((uint32_t)(ch ^ (rowA & 7))) << 4);
                ldsm_x4(ah[mt][0], ah[mt][1], ah[mt][2], ah[mt][3], sah + off);
                ldsm_x4(al[mt][0], al[mt][1], al[mt][2], al[mt][3], sal + off);
            }
            #pragma unroll
            for (int nt2 = 0; nt2 < 2; ++nt2) {
                int rowB = wn * 32 + nt2 * 16 + (lane & 7) + ((lane >> 3) & 1) * 8;
                uint32_t off = ((uint32_t)rowB << 7) + (((uint32_t)(ch ^ (rowB & 7))) << 4);
                uint32_t h0, h1, h2, h3;
                ldsm_x4(h0, h1, h2, h3, sbh + off);
                #pragma unroll
                for (int mt = 0; mt < 4; ++mt) {
                    mma16816(acc[mt][nt2 * 2 + 0], ah[mt], h0, h2);
                    mma16816(acc[mt][nt2 * 2 + 1], ah[mt], h1, h3);
                    mma16816(acc[mt][nt2 * 2 + 0], al[mt], h0, h2);
                    mma16816(acc[mt][nt2 * 2 + 1], al[mt], h1, h3);
                }
            }
        }
        __syncthreads();
        buf = (buf == 2) ? 0 : buf + 1;
        ibuf = (ibuf == 2) ? 0 : ibuf + 1;
    }
    #undef ISSUE_STAGE

    // -------- epilogue --------
    #pragma unroll
    for (int mt = 0; mt < 4; ++mt) {
        int m = m0 + wm * 64 + mt * 16 + (lane >> 2);
        #pragma unroll
        for (int nt = 0; nt < 4; ++nt) {
            int n = n0 + wn * 32 + nt * 8 + (lane & 3) * 2;
            float* p = C + (size_t)m * ldc + n;
            *(float2*)p = make_float2(acc[mt][nt][0], acc[mt][nt][1]);
            *(float2*)(p + 8 * (size_t)ldc) = make_float2(acc[mt][nt][2], acc[mt][nt][3]);
        }
    }
}

// ---------------- alpha_mean per head ----------------
__global__ void amean_kernel(const float* __restrict__ alpha_log) {
    int w = threadIdx.x >> 5;
    int lane = threadIdx.x & 31;
    float s = 0.f;
    for (int d = lane; d < DH_; d += 32)
        s += sigmoidf_(alpha_log[w * DH_ + d]);
    #pragma unroll
    for (int o = 16; o; o >>= 1) s += __shfl_xor_sync(0xffffffffu, s, o);
    if (lane == 0) g_amean[w] = s / (float)DH_;
}

// ---------------- beta = sigmoid(x @ Wb^T + bb) ----------------
__global__ __launch_bounds__(256) void beta_kernel(const float* __restrict__ x,
                                                   const float* __restrict__ Wb,
                                                   const float* __restrict__ bb,
                                                   float* __restrict__ beta) {
    __shared__ float xs[DM_];
    int row = blockIdx.x;
    for (int i = threadIdx.x; i < DM_; i += 256)
        xs[i] = x[row * DM_ + i];
    __syncthreads();
    int w = threadIdx.x >> 5;
    int lane = threadIdx.x & 31;
    const float* wr = Wb + w * DM_;
    float sum = 0.f;
    for (int i = lane; i < DM_; i += 32)
        sum += xs[i] * wr[i];
    #pragma unroll
    for (int o = 16; o; o >>= 1) sum += __shfl_xor_sync(0xffffffffu, sum, o);
    if (lane == 0) beta[row * H_ + w] = sigmoidf_(sum + bb[w]);
}

// ---------------- RoPE in-place on q and k ----------------
__global__ void rope_kernel(float* __restrict__ q, float* __restrict__ k) {
    int idx = blockIdx.x * blockDim.x + threadIdx.x;
    int j = idx & 63;
    int h = (idx >> 6) & (H_ - 1);
    int row = idx >> 9;
    int s = row & (S_ - 1);
    float ex = (float)(2 * j) * (1.0f / (float)DH_);
    float inv = powf(10000.0f, -ex);
    float ang = (float)s * inv;
    float sn, c;
    sincosf(ang, &sn, &c);
    int base = row * INNER_ + h * DH_ + j;
    float x1 = q[base], x2 = q[base + 64];
    q[base]      = x1 * c - x2 * sn;
    q[base + 64] = x2 * c + x1 * sn;
    x1 = k[base]; x2 = k[base + 64];
    k[base]      = x1 * c - x2 * sn;
    k[base + 64] = x2 * c + x1 * sn;
}

// ---------------- windowed decay attention (emits fp16 hi/lo) --------------
#define WIN_ 32
__global__ __launch_bounds__(256) void attn_kernel(const float* __restrict__ q,
                                                   const float* __restrict__ k,
                                                   const float* __restrict__ v,
                                                   const float* __restrict__ beta,
                                                   __half* __restrict__ ahi,
                                                   __half* __restrict__ alo) {
    int gw = (blockIdx.x * 256 + threadIdx.x) >> 5;
    int lane = threadIdx.x & 31;
    int s = gw & (S_ - 1);
    int h = (gw >> 11) & (H_ - 1);
    int b = gw >> 14;
    float am = g_amean[h];
    size_t colbase = (size_t)b * S_ * INNER_ + h * DH_ + lane * 4;
    float4 qv = *(const float4*)(q + colbase + (size_t)s * INNER_);
    float4 acc = make_float4(0.f, 0.f, 0.f, 0.f);
    float decay = 1.f;
    int t_lo = s - (WIN_ - 1); if (t_lo < 0) t_lo = 0;
    for (int t = s; t >= t_lo; t--) {
        float4 kv = *(const float4*)(k + colbase + (size_t)t * INNER_);
        float d = qv.x * kv.x + qv.y * kv.y + qv.z * kv.z + qv.w * kv.w;
        #pragma unroll
        for (int o = 16; o; o >>= 1) d += __shfl_xor_sync(0xffffffffu, d, o);
        float w = d * decay * beta[(b * S_ + t) * H_ + h];
        float4 vv = *(const float4*)(v + colbase + (size_t)t * INNER_);
        acc.x = fmaf(w, vv.x, acc.x);
        acc.y = fmaf(w, vv.y, acc.y);
        acc.z = fmaf(w, vv.z, acc.z);
        acc.w = fmaf(w, vv.w, acc.w);
        decay *= am;
    }
    size_t o = colbase + (size_t)s * INNER_;
    __half h0 = __float2half(acc.x);
    __half h1 = __float2half(acc.y);
    __half h2 = __float2half(acc.z);
    __half h3 = __float2half(acc.w);
    ((__half2*)(ahi + o))[0] = __half2(h0, h1);
    ((__half2*)(ahi + o))[1] = __half2(h2, h3);
    ((__half2*)(alo + o))[0] = __half2(__float2half(acc.x - __half2float(h0)),
                                       __float2half(acc.y - __half2float(h1)));
    ((__half2*)(alo + o))[1] = __half2(__float2half(acc.z - __half2float(h2)),
                                       __float2half(acc.w - __half2float(h3)));
}

// ---------------- final recurrent state (windowed scan) ----------------
#define STWIN_ 128
__global__ __launch_bounds__(256) void state_kernel(const float* __restrict__ k,
                                                    const float* __restrict__ v,
                                                    const float* __restrict__ beta,
                                                    const float* __restrict__ alpha_log,
                                                    float* __restrict__ stout) {
    int b = blockIdx.x >> 3;
    int h = blockIdx.x & 7;
    int tid = threadIdx.x;
    int d = tid >> 1;
    int e0 = (tid & 1) * 64;
    __shared__ float ks[DH_], vs[DH_];
    float st[64];
    #pragma unroll
    for (int e = 0; e < 64; e++) st[e] = 0.f;
    float ad = sigmoidf_(alpha_log[h * DH_ + d]);
    for (int t = S_ - STWIN_; t < S_; t++) {
        __syncthreads();
        size_t base = (size_t)(b * S_ + t) * INNER_ + h * DH_;
        if (tid < 128) ks[tid] = k[base + tid];
        else           vs[tid - 128] = v[base + tid - 128];
        __syncthreads();
        float kb = ks[d] * beta[(b * S_ + t) * H_ + h];
        #pragma unroll
        for (int e = 0; e < 64; e++)
            st[e] = fmaf(ad, st[e], kb * vs[e0 + e]);
    }
    float* op = stout + ((size_t)(b * H_ + h) * DH_ + d) * DH_ + e0;
    #pragma unroll
    for (int e = 0; e < 64; e++) op[e] = st[e];
}

// ---------------- launch ----------------
extern "C" void kernel_launch(void* const* d_in, const int* in_sizes, int n_in,
                              void* d_out, int out_size) {
    const float* x         = (const float*)d_in[0];
    const float* Wq        = (const float*)d_in[1];
    const float* Wk        = (const float*)d_in[2];
    const float* Wv        = (const float*)d_in[3];
    const float* Wo        = (const float*)d_in[4];
    const float* Wb        = (const float*)d_in[5];
    const float* bb        = (const float*)d_in[6];
    const float* alpha_log = (const float*)d_in[7];
    float* out = (float*)d_out;

    float *q, *k, *v, *beta;
    cudaGetSymbolAddress((void**)&q,    g_q);
    cudaGetSymbolAddress((void**)&k,    g_k);
    cudaGetSymbolAddress((void**)&v,    g_v);
    cudaGetSymbolAddress((void**)&beta, g_beta);
    __half *xhi, *xlo, *wqh, *wkh, *wvh, *woh, *ahi, *alo;
    cudaGetSymbolAddress((void**)&xhi, g_xhi);
    cudaGetSymbolAddress((void**)&xlo, g_xlo);
    cudaGetSymbolAddress((void**)&wqh, g_wqh);
    cudaGetSymbolAddress((void**)&wkh, g_wkh);
    cudaGetSymbolAddress((void**)&wvh, g_wvh);
    cudaGetSymbolAddress((void**)&woh, g_woh);
    cudaGetSymbolAddress((void**)&ahi, g_ahi);
    cudaGetSymbolAddress((void**)&alo, g_alo);

    cudaFuncSetAttribute(hmma_gemm, cudaFuncAttributeMaxDynamicSharedMemorySize, GEMM_SMEM);

    amean_kernel<<<1, 256>>>(alpha_log);
    beta_kernel<<<MROWS, 256>>>(x, Wb, bb, beta);

    // conversions
    splitA_kernel<<<(MROWS*DM_/4 + 255)/256, 256>>>(x, xhi, xlo, MROWS*DM_/4);
    cvt_kernel<<<(INNER_*DM_/4 + 255)/256, 256>>>(Wq, wqh, INNER_*DM_/4);
    cvt_kernel<<<(INNER_*DM_/4 + 255)/256, 256>>>(Wk, wkh, INNER_*DM_/4);
    cvt_kernel<<<(INNER_*DM_/4 + 255)/256, 256>>>(Wv, wvh, INNER_*DM_/4);
    cvt_kernel<<<(DM_*INNER_/4 + 255)/256, 256>>>(Wo, woh, DM_*INNER_/4);

    // QKV: fused 3-way GEMM, M=4096, N=1024, K=2048
    dim3 gqkv(INNER_/128, MROWS/128, 3);
    hmma_gemm<<<gqkv, 256, GEMM_SMEM>>>(xhi, xlo,
                                        wqh, wkh, wvh,
                                        q, k, v, DM_, INNER_);

    rope_kernel<<<(B_ * S_ * H_ * 64) / 256, 256>>>(q, k);
    attn_kernel<<<(B_ * H_ * S_) / 8, 256>>>(q, k, v, beta, ahi, alo);

    // O-proj: M=4096, N=2048, K=1024
    dim3 gout(DM_/128, MROWS/128, 1);
    hmma_gemm<<<gout, 256, GEMM_SMEM>>>(ahi, alo,
                                        woh, woh, woh,
                                        out, out, out, INNER_, DM_);

    state_kernel<<<B_ * H_, 256>>>(k, v, beta, alpha_log, out + (size_t)MROWS * DM_);
}

// round 7
// speedup vs baseline: 2.9010x; 1.1990x over previous
#include <cuda_runtime.h>
#include <cuda_fp16.h>
#include <math.h>
#include <stdint.h>

#define B_ 2
#define S_ 2048
#define DM_ 2048
#define H_ 8
#define DH_ 128
#define INNER_ 1024
#define MROWS (B_*S_)   // 4096

// ---------------- scratch (device globals; no allocation allowed) ----------
__device__ float g_q[MROWS * INNER_];
__device__ float g_k[MROWS * INNER_];
__device__ float g_v[MROWS * INNER_];
__device__ float g_beta[MROWS * H_];
__device__ float g_amean[H_];

__device__ __align__(128) __half g_xhi[MROWS * DM_];
__device__ __align__(128) __half g_xlo[MROWS * DM_];
__device__ __align__(128) __half g_wqh[INNER_ * DM_];
__device__ __align__(128) __half g_wkh[INNER_ * DM_];
__device__ __align__(128) __half g_wvh[INNER_ * DM_];
__device__ __align__(128) __half g_woh[DM_ * INNER_];
__device__ __align__(128) __half g_ahi[MROWS * INNER_];
__device__ __align__(128) __half g_alo[MROWS * INNER_];

#define STWIN_ 128
#define STCH 4
#define STLEN (STWIN_/STCH)   // 32
__device__ float g_stpart[B_ * H_ * STCH * DH_ * DH_];

__device__ __forceinline__ float sigmoidf_(float x) {
    return 1.0f / (1.0f + expf(-x));
}

// ======================= PTX helpers ==============================
__device__ __forceinline__ uint32_t smem_u32(const void* p) {
    uint32_t a;
    asm("{ .reg .u64 t; cvta.to.shared.u64 t, %1; cvt.u32.u64 %0, t; }"
        : "=r"(a) : "l"(p));
    return a;
}

#define CP_ASYNC16(dst, src) \
    asm volatile("cp.async.cg.shared.global [%0], [%1], 16;" :: "r"(dst), "l"(src) : "memory")
#define CP_COMMIT() asm volatile("cp.async.commit_group;" ::: "memory")
#define CP_WAIT(n)  asm volatile("cp.async.wait_group %0;" :: "n"(n) : "memory")

__device__ __forceinline__ void ldsm_x4(uint32_t& r0, uint32_t& r1, uint32_t& r2, uint32_t& r3,
                                        uint32_t addr) {
    asm volatile("ldmatrix.sync.aligned.m8n8.x4.shared.b16 {%0,%1,%2,%3}, [%4];"
        : "=r"(r0), "=r"(r1), "=r"(r2), "=r"(r3) : "r"(addr));
}

__device__ __forceinline__ void mma16816(float* c, const uint32_t* a, uint32_t b0, uint32_t b1) {
    asm volatile(
        "mma.sync.aligned.m16n8k16.row.col.f32.f16.f16.f32 "
        "{%0,%1,%2,%3}, {%4,%5,%6,%7}, {%8,%9}, {%0,%1,%2,%3};"
        : "+f"(c[0]), "+f"(c[1]), "+f"(c[2]), "+f"(c[3])
        : "r"(a[0]), "r"(a[1]), "r"(a[2]), "r"(a[3]), "r"(b0), "r"(b1));
}

// ======================= conversions ==========================
// fp32 -> fp16 hi/lo split (A operand: 22-bit exact)
__global__ void splitA_kernel(const float* __restrict__ src,
                              __half* __restrict__ hi,
                              __half* __restrict__ lo, int n4) {
    int i = blockIdx.x * blockDim.x + threadIdx.x;
    if (i >= n4) return;
    float4 v = ((const float4*)src)[i];
    __half h0 = __float2half(v.x);
    __half h1 = __float2half(v.y);
    __half h2 = __float2half(v.z);
    __half h3 = __float2half(v.w);
    __half l0 = __float2half(v.x - __half2float(h0));
    __half l1 = __float2half(v.y - __half2float(h1));
    __half l2 = __float2half(v.z - __half2float(h2));
    __half l3 = __float2half(v.w - __half2float(h3));
    __half2* hp = (__half2*)hi;
    __half2* lp = (__half2*)lo;
    hp[2*i]   = __half2(h0, h1);
    hp[2*i+1] = __half2(h2, h3);
    lp[2*i]   = __half2(l0, l1);
    lp[2*i+1] = __half2(l2, l3);
}

// fp32 -> fp16 for all four weight matrices (same element count each)
__global__ void cvt4_kernel(const float* __restrict__ s0, const float* __restrict__ s1,
                            const float* __restrict__ s2, const float* __restrict__ s3,
                            __half* __restrict__ d0, __half* __restrict__ d1,
                            __half* __restrict__ d2, __half* __restrict__ d3, int n4) {
    int i = blockIdx.x * blockDim.x + threadIdx.x;
    if (i >= n4) return;
    int seg = blockIdx.y;
    const float* s = (seg == 0) ? s0 : (seg == 1) ? s1 : (seg == 2) ? s2 : s3;
    __half* d = (seg == 0) ? d0 : (seg == 1) ? d1 : (seg == 2) ? d2 : d3;
    float4 v = ((const float4*)s)[i];
    __half2* p = (__half2*)d;
    p[2*i]   = __half2(__float2half(v.x), __float2half(v.y));
    p[2*i+1] = __half2(__float2half(v.z), __float2half(v.w));
}

// ======================= fp16 2-pass HMMA GEMM ==============================
// C[M,N](fp32) = (Ah+Al)[M,K] @ Bh[N,K]^T
// 128x128 CTA tile, k-chunk 64 halves (128B), 2-stage cp.async, 2 CTAs/SM.
#define NSTG 2
#define TILE_B 16384u                 // one operand tile: 128 rows x 128B
#define STG_BYTES (3u * TILE_B)       // Ah | Al | Bh = 48KB
#define GEMM_SMEM (NSTG * STG_BYTES)  // 96KB

__global__ __launch_bounds__(256, 2) void hmma_gemm(
    const __half* __restrict__ Ah, const __half* __restrict__ Al,
    const __half* __restrict__ B0, const __half* __restrict__ B1,
    const __half* __restrict__ B2,
    float* __restrict__ C0, float* __restrict__ C1, float* __restrict__ C2,
    int K, int ldc) {
    extern __shared__ char smem[];
    uint32_t sm = smem_u32(smem);
    int tid = threadIdx.x;
    int lane = tid & 31;
    int wid = tid >> 5;
    int wm = wid & 1;          // 2 M-blocks of 64
    int wn = wid >> 1;         // 4 N-blocks of 32
    int m0 = blockIdx.y * 128;
    int n0 = blockIdx.x * 128;

    const __half* Bh;
    float* C;
    if (blockIdx.z == 0)      { Bh = B0; C = C0; }
    else if (blockIdx.z == 1) { Bh = B1; C = C1; }
    else                      { Bh = B2; C = C2; }

    int kiters = K >> 6;

    float acc[4][4][4];
    #pragma unroll
    for (int i = 0; i < 4; i++)
        #pragma unroll
        for (int j = 0; j < 4; j++)
            #pragma unroll
            for (int t = 0; t < 4; t++) acc[i][j][t] = 0.f;

    int lc = tid & 7;          // 16B chunk col within 128B row
    int lr = tid >> 3;         // 0..31

    #define ISSUE_STAGE(ip, buf) do {                                          \
        int _k0 = (ip) << 6;                                                   \
        const __half* _ah = Ah + (size_t)(m0 + lr) * K + _k0 + lc * 8;         \
        const __half* _al = Al + (size_t)(m0 + lr) * K + _k0 + lc * 8;         \
        const __half* _bh = Bh + (size_t)(n0 + lr) * K + _k0 + lc * 8;         \
        uint32_t _sb = sm + (buf) * STG_BYTES;                                 \
        _Pragma("unroll")                                                      \
        for (int _i = 0; _i < 4; _i++) {                                       \
            int _row = lr + 32 * _i;                                           \
            uint32_t _sw = ((uint32_t)_row << 7) + (((uint32_t)(lc ^ (_row & 7))) << 4); \
            size_t _go = (size_t)(32 * _i) * K;                                \
            CP_ASYNC16(_sb + _sw,              _ah + _go);                     \
            CP_ASYNC16(_sb + TILE_B + _sw,     _al + _go);                     \
            CP_ASYNC16(_sb + 2*TILE_B + _sw,   _bh + _go);                     \
        }                                                                      \
    } while (0)

    ISSUE_STAGE(0, 0); CP_COMMIT();

    for (int it = 0; it < kiters; ++it) {
        if (it + 1 < kiters) {
            ISSUE_STAGE(it + 1, (it + 1) & 1);
            CP_COMMIT();
            CP_WAIT(1);
        } else {
            CP_WAIT(0);
        }
        __syncthreads();

        uint32_t sah = sm + (it & 1) * STG_BYTES;
        uint32_t sal = sah + TILE_B;
        uint32_t sbh = sah + 2 * TILE_B;
        #pragma unroll
        for (int ks = 0; ks < 4; ++ks) {
            int ch = ks * 2 + (lane >> 4);
            // B fragments for both 16-row groups first (low live-reg count)
            uint32_t bfr[2][4];
            #pragma unroll
            for (int nt2 = 0; nt2 < 2; ++nt2) {
                int rowB = wn * 32 + nt2 * 16 + (lane & 7) + ((lane >> 3) & 1) * 8;
                uint32_t off = ((uint32_t)rowB << 7) + (((uint32_t)(ch ^ (rowB & 7))) << 4);
                ldsm_x4(bfr[nt2][0], bfr[nt2][1], bfr[nt2][2], bfr[nt2][3], sbh + off);
            }
            #pragma unroll
            for (int mt = 0; mt < 4; ++mt) {
                int rowA = wm * 64 + mt * 16 + (lane & 7) + ((lane >> 3) & 1) * 8;
                uint32_t off = ((uint32_t)rowA << 7) + (((uint32_t)(ch ^ (rowA & 7))) << 4);
                uint32_t ah[4], al[4];
                ldsm_x4(ah[0], ah[1], ah[2], ah[3], sah + off);
                ldsm_x4(al[0], al[1], al[2], al[3], sal + off);
                #pragma unroll
                for (int nt2 = 0; nt2 < 2; ++nt2) {
                    mma16816(acc[mt][nt2 * 2 + 0], ah, bfr[nt2][0], bfr[nt2][2]);
                    mma16816(acc[mt][nt2 * 2 + 1], ah, bfr[nt2][1], bfr[nt2][3]);
                    mma16816(acc[mt][nt2 * 2 + 0], al, bfr[nt2][0], bfr[nt2][2]);
                    mma16816(acc[mt][nt2 * 2 + 1], al, bfr[nt2][1], bfr[nt2][3]);
                }
            }
        }
        __syncthreads();
    }
    #undef ISSUE_STAGE

    // -------- epilogue --------
    #pragma unroll
    for (int mt = 0; mt < 4; ++mt) {
        int m = m0 + wm * 64 + mt * 16 + (lane >> 2);
        #pragma unroll
        for (int nt = 0; nt < 4; ++nt) {
            int n = n0 + wn * 32 + nt * 8 + (lane & 3) * 2;
            float* p = C + (size_t)m * ldc + n;
            *(float2*)p = make_float2(acc[mt][nt][0], acc[mt][nt][1]);
            *(float2*)(p + 8 * (size_t)ldc) = make_float2(acc[mt][nt][2], acc[mt][nt][3]);
        }
    }
}

// ---------------- alpha_mean per head ----------------
__global__ void amean_kernel(const float* __restrict__ alpha_log) {
    int w = threadIdx.x >> 5;
    int lane = threadIdx.x & 31;
    float s = 0.f;
    for (int d = lane; d < DH_; d += 32)
        s += sigmoidf_(alpha_log[w * DH_ + d]);
    #pragma unroll
    for (int o = 16; o; o >>= 1) s += __shfl_xor_sync(0xffffffffu, s, o);
    if (lane == 0) g_amean[w] = s / (float)DH_;
}

// ---------------- beta = sigmoid(x @ Wb^T + bb) ----------------
__global__ __launch_bounds__(256) void beta_kernel(const float* __restrict__ x,
                                                   const float* __restrict__ Wb,
                                                   const float* __restrict__ bb,
                                                   float* __restrict__ beta) {
    __shared__ float xs[DM_];
    int row = blockIdx.x;
    for (int i = threadIdx.x; i < DM_; i += 256)
        xs[i] = x[row * DM_ + i];
    __syncthreads();
    int w = threadIdx.x >> 5;
    int lane = threadIdx.x & 31;
    const float* wr = Wb + w * DM_;
    float sum = 0.f;
    for (int i = lane; i < DM_; i += 32)
        sum += xs[i] * wr[i];
    #pragma unroll
    for (int o = 16; o; o >>= 1) sum += __shfl_xor_sync(0xffffffffu, sum, o);
    if (lane == 0) beta[row * H_ + w] = sigmoidf_(sum + bb[w]);
}

// ---------------- RoPE in-place on q and k ----------------
__global__ void rope_kernel(float* __restrict__ q, float* __restrict__ k) {
    int idx = blockIdx.x * blockDim.x + threadIdx.x;
    int j = idx & 63;
    int h = (idx >> 6) & (H_ - 1);
    int row = idx >> 9;
    int s = row & (S_ - 1);
    float ex = (float)(2 * j) * (1.0f / (float)DH_);
    float inv = powf(10000.0f, -ex);
    float ang = (float)s * inv;
    float sn, c;
    sincosf(ang, &sn, &c);
    int base = row * INNER_ + h * DH_ + j;
    float x1 = q[base], x2 = q[base + 64];
    q[base]      = x1 * c - x2 * sn;
    q[base + 64] = x2 * c + x1 * sn;
    x1 = k[base]; x2 = k[base + 64];
    k[base]      = x1 * c - x2 * sn;
    k[base + 64] = x2 * c + x1 * sn;
}

// ---------------- windowed decay attention (4-way ILP, emits fp16 hi/lo) ---
#define WIN_ 32
__global__ __launch_bounds__(256) void attn_kernel(const float* __restrict__ q,
                                                   const float* __restrict__ k,
                                                   const float* __restrict__ v,
                                                   const float* __restrict__ beta,
                                                   __half* __restrict__ ahi,
                                                   __half* __restrict__ alo) {
    int gw = (blockIdx.x * 256 + threadIdx.x) >> 5;
    int lane = threadIdx.x & 31;
    int s = gw & (S_ - 1);
    int h = (gw >> 11) & (H_ - 1);
    int b = gw >> 14;
    float am = g_amean[h];
    float am2 = am * am;
    float am3 = am2 * am;
    float am4 = am2 * am2;
    size_t colbase = (size_t)b * S_ * INNER_ + h * DH_ + lane * 4;
    const float4 qv = *(const float4*)(q + colbase + (size_t)s * INNER_);
    float4 acc = make_float4(0.f, 0.f, 0.f, 0.f);
    float decay = 1.f;
    int t_lo = s - (WIN_ - 1); if (t_lo < 0) t_lo = 0;
    const float* betab = beta + (size_t)b * S_ * H_ + h;

    for (int t4 = s; t4 >= t_lo; t4 -= 4) {
        int t1 = t4 - 1, t2 = t4 - 2, t3 = t4 - 3;
        bool m1 = t1 >= t_lo, m2 = t2 >= t_lo, m3 = t3 >= t_lo;
        float4 z = make_float4(0.f, 0.f, 0.f, 0.f);
        float4 k0 = *(const float4*)(k + colbase + (size_t)t4 * INNER_);
        float4 v0 = *(const float4*)(v + colbase + (size_t)t4 * INNER_);
        float4 k1 = m1 ? *(const float4*)(k + colbase + (size_t)t1 * INNER_) : z;
        float4 v1 = m1 ? *(const float4*)(v + colbase + (size_t)t1 * INNER_) : z;
        float4 k2 = m2 ? *(const float4*)(k + colbase + (size_t)t2 * INNER_) : z;
        float4 v2 = m2 ? *(const float4*)(v + colbase + (size_t)t2 * INNER_) : z;
        float4 k3 = m3 ? *(const float4*)(k + colbase + (size_t)t3 * INNER_) : z;
        float4 v3 = m3 ? *(const float4*)(v + colbase + (size_t)t3 * INNER_) : z;
        float d0 = qv.x*k0.x + qv.y*k0.y + qv.z*k0.z + qv.w*k0.w;
        float d1 = qv.x*k1.x + qv.y*k1.y + qv.z*k1.z + qv.w*k1.w;
        float d2 = qv.x*k2.x + qv.y*k2.y + qv.z*k2.z + qv.w*k2.w;
        float d3 = qv.x*k3.x + qv.y*k3.y + qv.z*k3.z + qv.w*k3.w;
        #pragma unroll
        for (int o = 16; o; o >>= 1) {
            d0 += __shfl_xor_sync(0xffffffffu, d0, o);
            d1 += __shfl_xor_sync(0xffffffffu, d1, o);
            d2 += __shfl_xor_sync(0xffffffffu, d2, o);
            d3 += __shfl_xor_sync(0xffffffffu, d3, o);
        }
        float bt0 = betab[(size_t)t4 * H_];
        float bt1 = m1 ? betab[(size_t)t1 * H_] : 0.f;
        float bt2 = m2 ? betab[(size_t)t2 * H_] : 0.f;
        float bt3 = m3 ? betab[(size_t)t3 * H_] : 0.f;
        float w0 = d0 * decay * bt0;
        float w1 = d1 * decay * am  * bt1;
        float w2 = d2 * decay * am2 * bt2;
        float w3 = d3 * decay * am3 * bt3;
        acc.x = fmaf(w0, v0.x, fmaf(w1, v1.x, fmaf(w2, v2.x, fmaf(w3, v3.x, acc.x))));
        acc.y = fmaf(w0, v0.y, fmaf(w1, v1.y, fmaf(w2, v2.y, fmaf(w3, v3.y, acc.y))));
        acc.z = fmaf(w0, v0.z, fmaf(w1, v1.z, fmaf(w2, v2.z, fmaf(w3, v3.z, acc.z))));
        acc.w = fmaf(w0, v0.w, fmaf(w1, v1.w, fmaf(w2, v2.w, fmaf(w3, v3.w, acc.w))));
        decay *= am4;
    }
    size_t o = colbase + (size_t)s * INNER_;
    __half h0 = __float2half(acc.x);
    __half h1 = __float2half(acc.y);
    __half h2 = __float2half(acc.z);
    __half h3 = __float2half(acc.w);
    ((__half2*)(ahi + o))[0] = __half2(h0, h1);
    ((__half2*)(ahi + o))[1] = __half2(h2, h3);
    ((__half2*)(alo + o))[0] = __half2(__float2half(acc.x - __half2float(h0)),
                                       __float2half(acc.y - __half2float(h1)));
    ((__half2*)(alo + o))[1] = __half2(__float2half(acc.z - __half2float(h2)),
                                       __float2half(acc.w - __half2float(h3)));
}

// ---------------- recurrent state: partial chunks + combine ----------------
__global__ __launch_bounds__(256) void state_part(const float* __restrict__ k,
                                                  const float* __restrict__ v,
                                                  const float* __restrict__ beta,
                                                  const float* __restrict__ alpha_log,
                                                  float* __restrict__ part) {
    int bh = blockIdx.x >> 2;        // 0..15
    int c  = blockIdx.x & 3;
    int b = bh >> 3;
    int h = bh & 7;
    int tid = threadIdx.x;
    int d = tid >> 1;
    int e0 = (tid & 1) * 64;
    __shared__ float ks[DH_], vs[DH_];
    float st[64];
    #pragma unroll
    for (int e = 0; e < 64; e++) st[e] = 0.f;
    float ad = sigmoidf_(alpha_log[h * DH_ + d]);
    int tbeg = S_ - STWIN_ + c * STLEN;
    for (int t = tbeg; t < tbeg + STLEN; t++) {
        __syncthreads();
        size_t base = (size_t)(b * S_ + t) * INNER_ + h * DH_;
        if (tid < 128) ks[tid] = k[base + tid];
        else           vs[tid - 128] = v[base + tid - 128];
        __syncthreads();
        float kb = ks[d] * beta[(b * S_ + t) * H_ + h];
        #pragma unroll
        for (int e = 0; e < 64; e++)
            st[e] = fmaf(ad, st[e], kb * vs[e0 + e]);
    }
    float* op = part + (((size_t)bh * STCH + c) * DH_ + d) * DH_ + e0;
    #pragma unroll
    for (int e = 0; e < 64; e++) op[e] = st[e];
}

__global__ __launch_bounds__(256) void state_comb(const float* __restrict__ part,
                                                  const float* __restrict__ alpha_log,
                                                  float* __restrict__ stout) {
    int bh = blockIdx.x;             // 0..15
    int h = bh & 7;
    int tid = threadIdx.x;
    int d = tid >> 1;
    int e0 = (tid & 1) * 64;
    float ad = sigmoidf_(alpha_log[h * DH_ + d]);
    // ad^STLEN (STLEN = 32): 5 squarings
    float a32 = ad;
    a32 *= a32; a32 *= a32; a32 *= a32; a32 *= a32; a32 *= a32;
    const float* p0 = part + (((size_t)bh * STCH + 0) * DH_ + d) * DH_ + e0;
    const float* p1 = part + (((size_t)bh * STCH + 1) * DH_ + d) * DH_ + e0;
    const float* p2 = part + (((size_t)bh * STCH + 2) * DH_ + d) * DH_ + e0;
    const float* p3 = part + (((size_t)bh * STCH + 3) * DH_ + d) * DH_ + e0;
    float* op = stout + ((size_t)bh * DH_ + d) * DH_ + e0;
    #pragma unroll
    for (int e = 0; e < 64; e++) {
        float r = p0[e];
        r = fmaf(r, a32, p1[e]);
        r = fmaf(r, a32, p2[e]);
        r = fmaf(r, a32, p3[e]);
        op[e] = r;
    }
}

// ---------------- launch ----------------
extern "C" void kernel_launch(void* const* d_in, const int* in_sizes, int n_in,
                              void* d_out, int out_size) {
    const float* x         = (const float*)d_in[0];
    const float* Wq        = (const float*)d_in[1];
    const float* Wk        = (const float*)d_in[2];
    const float* Wv        = (const float*)d_in[3];
    const float* Wo        = (const float*)d_in[4];
    const float* Wb        = (const float*)d_in[5];
    const float* bb        = (const float*)d_in[6];
    const float* alpha_log = (const float*)d_in[7];
    float* out = (float*)d_out;

    float *q, *k, *v, *beta, *stpart;
    cudaGetSymbolAddress((void**)&q,      g_q);
    cudaGetSymbolAddress((void**)&k,      g_k);
    cudaGetSymbolAddress((void**)&v,      g_v);
    cudaGetSymbolAddress((void**)&beta,   g_beta);
    cudaGetSymbolAddress((void**)&stpart, g_stpart);
    __half *xhi, *xlo, *wqh, *wkh, *wvh, *woh, *ahi, *alo;
    cudaGetSymbolAddress((void**)&xhi, g_xhi);
    cudaGetSymbolAddress((void**)&xlo, g_xlo);
    cudaGetSymbolAddress((void**)&wqh, g_wqh);
    cudaGetSymbolAddress((void**)&wkh, g_wkh);
    cudaGetSymbolAddress((void**)&wvh, g_wvh);
    cudaGetSymbolAddress((void**)&woh, g_woh);
    cudaGetSymbolAddress((void**)&ahi, g_ahi);
    cudaGetSymbolAddress((void**)&alo, g_alo);

    cudaFuncSetAttribute(hmma_gemm, cudaFuncAttributeMaxDynamicSharedMemorySize, GEMM_SMEM);

    amean_kernel<<<1, 256>>>(alpha_log);
    beta_kernel<<<MROWS, 256>>>(x, Wb, bb, beta);

    // conversions
    splitA_kernel<<<(MROWS*DM_/4 + 255)/256, 256>>>(x, xhi, xlo, MROWS*DM_/4);
    dim3 gcvt((INNER_*DM_/4 + 255)/256, 4);
    cvt4_kernel<<<gcvt, 256>>>(Wq, Wk, Wv, Wo, wqh, wkh, wvh, woh, INNER_*DM_/4);

    // QKV: fused 3-way GEMM, M=4096, N=1024, K=2048
    dim3 gqkv(INNER_/128, MROWS/128, 3);
    hmma_gemm<<<gqkv, 256, GEMM_SMEM>>>(xhi, xlo,
                                        wqh, wkh, wvh,
                                        q, k, v, DM_, INNER_);

    rope_kernel<<<(B_ * S_ * H_ * 64) / 256, 256>>>(q, k);
    attn_kernel<<<(B_ * H_ * S_) / 8, 256>>>(q, k, v, beta, ahi, alo);

    // O-proj: M=4096, N=2048, K=1024
    dim3 gout(DM_/128, MROWS/128, 1);
    hmma_gemm<<<gout, 256, GEMM_SMEM>>>(ahi, alo,
                                        woh, woh, woh,
                                        out, out, out, INNER_, DM_);

    // recurrent state (parallel chunks + combine)
    state_part<<<B_ * H_ * STCH, 256>>>(k, v, beta, alpha_log, stpart);
    state_comb<<<B_ * H_, 256>>>(stpart, alpha_log, out + (size_t)MROWS * DM_);
}